// round 6
// baseline (speedup 1.0000x reference)
#include <cuda_runtime.h>
#include <cuda_bf16.h>
#include <cstdint>

// fid[p] = clip( (va.vb)^2 / (|va|^2 |vb|^2), 0, 1 )
// va = tanh( relu(xa @ W1 + b1) @ W2 + b2 )   (quantum circuit is unitary -> cancels)
// GEMM1 via mma.sync m16n8k16 bf16 split hi/lo (3 MMAs). 64x64 warp tiles, M=256/block.
// W1 pre-converted to K-major bf16 hi/lo by a prepass kernel; B tiles staged with cp.async.

#define KDIM   784
#define KC     16
#define NCHUNK 49
#define ASTR   24      // uint16 elems per smem row (48 B): conflict-free frags + STS.128 staging
#define HSTR   65
#define VSTR   17

// dynamic smem byte offsets
#define OFF_A_HI(b) ((b) * 12288)              // 256*24*2B per buffer
#define OFF_A_LO(b) (24576 + (b) * 12288)
#define OFF_B_HI(b) (49152 + (b) * 3072)       // 64*24*2B per buffer
#define OFF_B_LO(b) (55296 + (b) * 3072)
#define OFF_H    0                              // epilogue overlay: 128*65*4 = 33280
#define OFF_VS   61440                          // 256*17*4 = 17408
#define OFF_SSQ  78848                          // 256*4
#define OFF_W2   79872                          // 64*16*4
#define OFF_B1   83968
#define OFF_B2   84224
#define SMEM_BYTES 84288

__device__ uint16_t g_W1T_hi[64 * KDIM];   // K-major: [n][k]
__device__ uint16_t g_W1T_lo[64 * KDIM];

#define MMA(d, a, b) asm volatile( \
    "mma.sync.aligned.m16n8k16.row.col.f32.bf16.bf16.f32 " \
    "{%0,%1,%2,%3}, {%4,%5,%6,%7}, {%8,%9}, {%0,%1,%2,%3};" \
    : "+f"(d[0]), "+f"(d[1]), "+f"(d[2]), "+f"(d[3]) \
    : "r"(a[0]), "r"(a[1]), "r"(a[2]), "r"(a[3]), "r"(b[0]), "r"(b[1]))

__device__ __forceinline__ uint32_t bf2u(__nv_bfloat162 v) { return *(uint32_t*)&v; }

__device__ __forceinline__ uint32_t hi2(float x, float y, uint32_t& lo) {
    __nv_bfloat162 h = __float22bfloat162_rn(make_float2(x, y));
    __nv_bfloat162 l = __float22bfloat162_rn(make_float2(
        x - __bfloat162float(h.x), y - __bfloat162float(h.y)));
    lo = bf2u(l);
    return bf2u(h);
}

// convert 8 floats -> 16B hi + 16B lo, single STS.128 each (conflict-free at 48B row stride)
__device__ __forceinline__ void cvst8(float4 a, float4 b, void* hip, void* lop) {
    uint4 h, l;
    h.x = hi2(a.x, a.y, l.x);
    h.y = hi2(a.z, a.w, l.y);
    h.z = hi2(b.x, b.y, l.z);
    h.w = hi2(b.z, b.w, l.w);
    *(uint4*)hip = h;
    *(uint4*)lop = l;
}

__device__ __forceinline__ void cp16(uint32_t dst, const void* src) {
    asm volatile("cp.async.ca.shared.global [%0], [%1], 16;" :: "r"(dst), "l"(src));
}

__global__ void prep_w1(const float* __restrict__ W1) {
    int i = blockIdx.x * 256 + threadIdx.x;        // 12544 = 64 * 196
    int n  = i / 196;
    int k4 = (i - n * 196) * 4;
    uint32_t h0, h1, l0, l1;
    {
        float v0 = W1[(size_t)(k4 + 0) * 64 + n];
        float v1 = W1[(size_t)(k4 + 1) * 64 + n];
        float v2 = W1[(size_t)(k4 + 2) * 64 + n];
        float v3 = W1[(size_t)(k4 + 3) * 64 + n];
        h0 = hi2(v0, v1, l0);
        h1 = hi2(v2, v3, l1);
    }
    *(uint2*)&g_W1T_hi[n * KDIM + k4] = make_uint2(h0, h1);
    *(uint2*)&g_W1T_lo[n * KDIM + k4] = make_uint2(l0, l1);
}

__global__ __launch_bounds__(128, 2)
void qcm_mma(const float* __restrict__ img_a,
             const float* __restrict__ img_b,
             const float* __restrict__ b1,
             const float* __restrict__ W2,
             const float* __restrict__ b2,
             float* __restrict__ out)
{
    extern __shared__ char smem[];
    const uint32_t sb = (uint32_t)__cvta_generic_to_shared(smem);

    float* W2s = (float*)(smem + OFF_W2);
    float* b1s = (float*)(smem + OFF_B1);
    float* b2s = (float*)(smem + OFF_B2);

    const int t    = threadIdx.x;
    const int lane = t & 31;
    const int wid  = t >> 5;          // 4 warps, each owns 64 rows
    const int g    = lane >> 2;
    const int tig  = lane & 3;
    const int rbase = wid * 64;
    const int p0   = blockIdx.x * 128;   // 128 pairs per block (256 rows)

    // params
    if (t < 64) b1s[t] = b1[t];
    if (t < 16) b2s[t] = b2[t];
    #pragma unroll
    for (int i = 0; i < 8; ++i) W2s[t + i * 128] = W2[t + i * 128];

    // staging: thread t owns rows t (img_a) and 128+t (img_b)
    const float* rowA = img_a + (size_t)(p0 + t) * KDIM;
    const float* rowB = img_b + (size_t)(p0 + t) * KDIM;

    float acc[4][8][4];
    #pragma unroll
    for (int mt = 0; mt < 4; ++mt)
        #pragma unroll
        for (int nt = 0; nt < 8; ++nt)
            #pragma unroll
            for (int j = 0; j < 4; ++j) acc[mt][nt][j] = 0.f;

    // ---- prologue: stage chunk 0 ----
    #pragma unroll
    for (int rep = 0; rep < 2; ++rep) {
        int o    = t + rep * 128;
        int hl   = o >> 7;
        int rem  = o & 127;
        int n    = rem >> 1;
        int half = rem & 1;
        const uint16_t* src = (hl ? g_W1T_lo : g_W1T_hi) + n * KDIM + half * 8;
        uint32_t dst = sb + (hl ? OFF_B_LO(0) : OFF_B_HI(0)) + n * 48 + half * 16;
        cp16(dst, src);
    }
    asm volatile("cp.async.commit_group;" ::: "memory");
    {
        float4 a0 = *(const float4*)(rowA + 0), a1 = *(const float4*)(rowA + 4);
        float4 a2 = *(const float4*)(rowA + 8), a3 = *(const float4*)(rowA + 12);
        float4 b0 = *(const float4*)(rowB + 0), b1v = *(const float4*)(rowB + 4);
        float4 b2v = *(const float4*)(rowB + 8), b3 = *(const float4*)(rowB + 12);
        cvst8(a0, a1, smem + OFF_A_HI(0) + t * 48,            smem + OFF_A_LO(0) + t * 48);
        cvst8(a2, a3, smem + OFF_A_HI(0) + t * 48 + 16,       smem + OFF_A_LO(0) + t * 48 + 16);
        cvst8(b0, b1v, smem + OFF_A_HI(0) + (128 + t) * 48,    smem + OFF_A_LO(0) + (128 + t) * 48);
        cvst8(b2v, b3, smem + OFF_A_HI(0) + (128 + t) * 48 + 16, smem + OFF_A_LO(0) + (128 + t) * 48 + 16);
    }
    asm volatile("cp.async.wait_group 0;" ::: "memory");
    __syncthreads();

    // ---- mainloop ----
    for (int c = 0; c < NCHUNK; ++c) {
        const int st = c & 1;
        const int nb = st ^ 1;
        const bool more = (c + 1 < NCHUNK);

        float4 pa0, pa1, pa2, pa3, pb0, pb1, pb2, pb3;
        if (more) {
            const int k1 = (c + 1) * KC;
            // issue cp.async for next B tile
            #pragma unroll
            for (int rep = 0; rep < 2; ++rep) {
                int o    = t + rep * 128;
                int hl   = o >> 7;
                int rem  = o & 127;
                int n    = rem >> 1;
                int half = rem & 1;
                const uint16_t* src = (hl ? g_W1T_lo : g_W1T_hi) + n * KDIM + k1 + half * 8;
                uint32_t dst = sb + (hl ? OFF_B_LO(nb) : OFF_B_HI(nb)) + n * 48 + half * 16;
                cp16(dst, src);
            }
            asm volatile("cp.async.commit_group;" ::: "memory");
            // prefetch next A rows into registers
            pa0 = *(const float4*)(rowA + k1 + 0);  pa1 = *(const float4*)(rowA + k1 + 4);
            pa2 = *(const float4*)(rowA + k1 + 8);  pa3 = *(const float4*)(rowA + k1 + 12);
            pb0 = *(const float4*)(rowB + k1 + 0);  pb1 = *(const float4*)(rowB + k1 + 4);
            pb2 = *(const float4*)(rowB + k1 + 8);  pb3 = *(const float4*)(rowB + k1 + 12);
        }

        const uint16_t* Ah = (const uint16_t*)(smem + OFF_A_HI(st));
        const uint16_t* Al = (const uint16_t*)(smem + OFF_A_LO(st));
        const uint16_t* Bh = (const uint16_t*)(smem + OFF_B_HI(st));
        const uint16_t* Bl = (const uint16_t*)(smem + OFF_B_LO(st));

        uint32_t bh[8][2], bl[8][2];
        #pragma unroll
        for (int nt = 0; nt < 8; ++nt) {
            int bb = (nt * 8 + g) * ASTR + 2 * tig;
            bh[nt][0] = *(const uint32_t*)&Bh[bb];
            bh[nt][1] = *(const uint32_t*)&Bh[bb + 8];
            bl[nt][0] = *(const uint32_t*)&Bl[bb];
            bl[nt][1] = *(const uint32_t*)&Bl[bb + 8];
        }

        #pragma unroll
        for (int mt = 0; mt < 4; ++mt) {
            int r0 = (rbase + mt * 16 + g) * ASTR + 2 * tig;
            uint32_t ah[4], al[4];
            ah[0] = *(const uint32_t*)&Ah[r0];
            ah[1] = *(const uint32_t*)&Ah[r0 + 8 * ASTR];
            ah[2] = *(const uint32_t*)&Ah[r0 + 8];
            ah[3] = *(const uint32_t*)&Ah[r0 + 8 * ASTR + 8];
            al[0] = *(const uint32_t*)&Al[r0];
            al[1] = *(const uint32_t*)&Al[r0 + 8 * ASTR];
            al[2] = *(const uint32_t*)&Al[r0 + 8];
            al[3] = *(const uint32_t*)&Al[r0 + 8 * ASTR + 8];
            #pragma unroll
            for (int nt = 0; nt < 8; ++nt) {
                MMA(acc[mt][nt], ah, bh[nt]);
                MMA(acc[mt][nt], ah, bl[nt]);
                MMA(acc[mt][nt], al, bh[nt]);
            }
        }

        if (more) {
            cvst8(pa0, pa1, smem + OFF_A_HI(nb) + t * 48,              smem + OFF_A_LO(nb) + t * 48);
            cvst8(pa2, pa3, smem + OFF_A_HI(nb) + t * 48 + 16,         smem + OFF_A_LO(nb) + t * 48 + 16);
            cvst8(pb0, pb1, smem + OFF_A_HI(nb) + (128 + t) * 48,      smem + OFF_A_LO(nb) + (128 + t) * 48);
            cvst8(pb2, pb3, smem + OFF_A_HI(nb) + (128 + t) * 48 + 16, smem + OFF_A_LO(nb) + (128 + t) * 48 + 16);
        }
        asm volatile("cp.async.wait_group 0;" ::: "memory");
        __syncthreads();
    }

    // ---- epilogue, two half-passes through H (overlays mainloop smem) ----
    float* Hs  = (float*)(smem + OFF_H);
    float* Vs  = (float*)(smem + OFF_VS);
    float* SSQ = (float*)(smem + OFF_SSQ);

    #pragma unroll
    for (int h = 0; h < 2; ++h) {
        // scatter relu(acc + b1) for mt in {2h, 2h+1}: global rows wid*64 + 32h + [0,32)
        #pragma unroll
        for (int m2 = 0; m2 < 2; ++m2) {
            int mt = 2 * h + m2;
            int lr = wid * 32 + m2 * 16 + g;
            #pragma unroll
            for (int nt = 0; nt < 8; ++nt) {
                int col = nt * 8 + 2 * tig;
                float bx = b1s[col], by = b1s[col + 1];
                Hs[lr * HSTR + col]           = fmaxf(acc[mt][nt][0] + bx, 0.f);
                Hs[lr * HSTR + col + 1]       = fmaxf(acc[mt][nt][1] + by, 0.f);
                Hs[(lr + 8) * HSTR + col]     = fmaxf(acc[mt][nt][2] + bx, 0.f);
                Hs[(lr + 8) * HSTR + col + 1] = fmaxf(acc[mt][nt][3] + by, 0.f);
            }
        }
        __syncthreads();

        // v = tanh(H @ W2 + b2): one row per thread
        {
            int lr = t;
            int gr = (t >> 5) * 64 + 32 * h + (t & 31);
            float s[16];
            #pragma unroll
            for (int j = 0; j < 16; ++j) s[j] = b2s[j];
            #pragma unroll 8
            for (int kk = 0; kk < 64; ++kk) {
                float hh = Hs[lr * HSTR + kk];
                const float4* w = (const float4*)&W2s[kk * 16];
                float4 w0 = w[0], w1 = w[1], w2 = w[2], w3 = w[3];
                s[0]  += hh * w0.x; s[1]  += hh * w0.y; s[2]  += hh * w0.z; s[3]  += hh * w0.w;
                s[4]  += hh * w1.x; s[5]  += hh * w1.y; s[6]  += hh * w1.z; s[7]  += hh * w1.w;
                s[8]  += hh * w2.x; s[9]  += hh * w2.y; s[10] += hh * w2.z; s[11] += hh * w2.w;
                s[12] += hh * w3.x; s[13] += hh * w3.y; s[14] += hh * w3.z; s[15] += hh * w3.w;
            }
            float sq = 0.f;
            #pragma unroll
            for (int j = 0; j < 16; ++j) { s[j] = tanhf(s[j]); sq += s[j] * s[j]; }
            #pragma unroll
            for (int j = 0; j < 16; ++j) Vs[gr * VSTR + j] = s[j];
            SSQ[gr] = sq;
        }
        __syncthreads();
    }

    // ---- fid = (va.vb)^2 / (|va|^2 |vb|^2), clipped ----
    {
        int p = t;   // 0..127
        float d = 0.f;
        #pragma unroll
        for (int j = 0; j < 16; ++j)
            d += Vs[p * VSTR + j] * Vs[(p + 128) * VSTR + j];
        float fid = (d * d) / (SSQ[p] * SSQ[p + 128]);
        out[p0 + p] = fminf(fmaxf(fid, 0.f), 1.f);
    }
}

extern "C" void kernel_launch(void* const* d_in, const int* in_sizes, int n_in,
                              void* d_out, int out_size)
{
    const float* img_a = (const float*)d_in[0];
    const float* img_b = (const float*)d_in[1];
    const float* W1    = (const float*)d_in[2];
    const float* b1    = (const float*)d_in[3];
    const float* W2    = (const float*)d_in[4];
    const float* b2    = (const float*)d_in[5];
    // d_in[6] = theta: unused — the circuit is unitary, fidelity is invariant.
    float* out = (float*)d_out;

    cudaFuncSetAttribute(qcm_mma, cudaFuncAttributeMaxDynamicSharedMemorySize, SMEM_BYTES);
    prep_w1<<<49, 256>>>(W1);                       // 12544 threads: W1 -> K-major bf16 hi/lo
    int blocks = out_size / 128;                    // 512
    qcm_mma<<<blocks, 128, SMEM_BYTES>>>(img_a, img_b, b1, W2, b2, out);
}